// round 15
// baseline (speedup 1.0000x reference)
#include <cuda_runtime.h>
#include <math_constants.h>
#include <cstdint>

#define BATCH 16
#define SEQ   4096
#define RANKS 8
#define PER   512
#define NTC   512
#define NEG   (-CUDART_INF_F)

__device__ __forceinline__ void st_remote_f32(float* lp, unsigned int r, float v) {
    unsigned int la = (unsigned int)__cvta_generic_to_shared((void*)lp);
    unsigned int ra;
    asm("mapa.shared::cluster.u32 %0, %1, %2;" : "=r"(ra) : "r"(la), "r"(r));
    asm volatile("st.shared::cluster.f32 [%0], %1;" :: "r"(ra), "f"(v) : "memory");
}
__device__ __forceinline__ void st_remote_s32(int* lp, unsigned int r, int v) {
    unsigned int la = (unsigned int)__cvta_generic_to_shared((void*)lp);
    unsigned int ra;
    asm("mapa.shared::cluster.u32 %0, %1, %2;" : "=r"(ra) : "r"(la), "r"(r));
    asm volatile("st.shared::cluster.b32 [%0], %1;" :: "r"(ra), "r"(v) : "memory");
}
#define CLUSTER_SYNC() do { \
    asm volatile("barrier.cluster.arrive.aligned;" ::: "memory"); \
    asm volatile("barrier.cluster.wait.aligned;"   ::: "memory"); } while (0)

__global__ __launch_bounds__(NTC, 1) __cluster_dims__(RANKS, 1, 1)
void pred_head_c2(const float* __restrict__ start_logits,
                  const float* __restrict__ end_logits,
                  float* __restrict__ out) {
    __shared__ float pfx_e[544];     // [0..511] own end-logit prefix; [512..541] next-chunk halo
    __shared__ float sfx_s[544];     // [32..543] own start-logit suffix; [2..31] prev-chunk halo
    __shared__ float s_parts[128];   // per-warp start sums from all 8 ranks (rank*16+wid)
    __shared__ float e_parts[128];   // per-warp end sums
    __shared__ float wsv[128];       // rank0 only: per-warp start winners (value)
    __shared__ int   wsi[128];       //                                      (index)
    __shared__ float wev[128];       // rank0 only: per-warp end winners
    __shared__ int   wei[128];

    const int t = threadIdx.x;
    const int lane = t & 31;
    const int wid  = t >> 5;
    unsigned int rank;
    asm("mov.u32 %0, %%cluster_ctarank;" : "=r"(rank));
    const int row = blockIdx.x >> 3;
    const int col = (int)rank * PER + t;
    const float* srow = start_logits + row * SEQ;
    const float* erow = end_logits   + row * SEQ;
    const int slot = (int)rank * 16 + wid;     // unique per (rank, warp)

    // ---- own logit loads (argmax path starts here) ----
    const float sl = srow[col];
    const float el = erow[col];

    // ---- halo recompute from gmem (log space; no cross-CTA exchange) ----
    if (wid == 1 && lane < 30) {
        float hv = (rank > 0) ? srow[(int)rank * PER - 30 + lane] : NEG;
        #pragma unroll
        for (int o = 1; o < 32; o <<= 1) {
            float b = __shfl_down_sync(0x3fffffffu, hv, o);
            if (lane + o < 30) hv = fmaxf(hv, b);
        }
        sfx_s[2 + lane] = hv;      // prev-chunk suffix of start-logit
    }
    if (wid == 2 && lane < 30) {
        float hv = (rank < RANKS - 1) ? erow[((int)rank + 1) * PER + lane] : NEG;
        #pragma unroll
        for (int o = 1; o < 32; o <<= 1) {
            float a = __shfl_up_sync(0x3fffffffu, hv, o);
            if (lane >= o) hv = fmaxf(hv, a);
        }
        pfx_e[512 + lane] = hv;    // next-chunk prefix of end-logit
    }

    // ---- per-warp prefix/suffix maxima on logits ----
    float pe = el, se_ = el;   // prefix/suffix of end-logit
    float ps_ = sl, ssx = sl;  // prefix/suffix of start-logit
    #pragma unroll
    for (int o = 1; o < 32; o <<= 1) {
        float a = __shfl_up_sync(0xffffffffu, pe, o);    if (lane >= o)     pe  = fmaxf(pe, a);
        float b = __shfl_down_sync(0xffffffffu, se_, o); if (lane + o < 32) se_ = fmaxf(se_, b);
        float c = __shfl_up_sync(0xffffffffu, ps_, o);   if (lane >= o)     ps_ = fmaxf(ps_, c);
        float d = __shfl_down_sync(0xffffffffu, ssx, o); if (lane + o < 32) ssx = fmaxf(ssx, d);
    }
    pfx_e[t] = pe;
    sfx_s[32 + t] = ssx;

    // ---- exps (MUFU; off argmax chain) + per-warp sums, pushed IMMEDIATELY ----
    const float sv = __expf(sl);
    const float ev = __expf(el);
    float a = sv, c = ev;
    #pragma unroll
    for (int o = 16; o; o >>= 1) {
        a += __shfl_xor_sync(0xffffffffu, a, o);
        c += __shfl_xor_sync(0xffffffffu, c, o);
    }
    // all lanes hold warp sums; lanes 0-7 ship start-sum, 8-15 ship end-sum (one rank each)
    if (lane < 8)        st_remote_f32(&s_parts[slot], (unsigned int)lane, a);
    else if (lane < 16)  st_remote_f32(&e_parts[slot], (unsigned int)(lane - 8), c);

    __syncthreads();   // the ONLY CTA barrier: scan arrays + halos visible

    // ---- width-31 windows via prefix/suffix decomposition (log space) ----
    const float pe30 = __shfl_sync(0xffffffffu, pe, 30);
    const float ss1  = __shfl_sync(0xffffffffu, ssx, 1);
    float F, Bv;
    if (lane == 0)       F = pe30;
    else if (lane == 1)  F = se_;
    else                 F = fmaxf(se_, pfx_e[t + 30]);
    if (lane == 31)      Bv = ss1;
    else if (lane == 30) Bv = ps_;
    else                 Bv = fmaxf(ps_, sfx_s[t + 2]);

    // ---- log-space scores + warp argmax (dual, first-index tie-break) ----
    float bsv = sl + F;  int bsi = col;
    float bev = el + Bv; int bei = col;
    #pragma unroll
    for (int o = 16; o; o >>= 1) {
        float ov = __shfl_xor_sync(0xffffffffu, bsv, o);
        int   oi = __shfl_xor_sync(0xffffffffu, bsi, o);
        if (ov > bsv || (ov == bsv && oi < bsi)) { bsv = ov; bsi = oi; }
        float ov2 = __shfl_xor_sync(0xffffffffu, bev, o);
        int   oi2 = __shfl_xor_sync(0xffffffffu, bei, o);
        if (ov2 > bev || (ov2 == bev && oi2 < bei)) { bev = ov2; bei = oi2; }
    }
    // every warp pushes its OWN winner straight to rank 0 (no bar2, no CTA fold)
    if (lane == 0) { st_remote_f32(&wsv[slot], 0u, bsv); st_remote_s32(&wsi[slot], 0u, bsi); }
    if (lane == 1) { st_remote_f32(&wev[slot], 0u, bev); st_remote_s32(&wei[slot], 0u, bei); }

    CLUSTER_SYNC();   // arrive=release / wait=acquire: all DSMEM pushes visible

    // ---- fold 128+128 sum partials (lanes 0-15: start, 16-31: end; 8 each) ----
    {
        const float* part = (lane < 16) ? s_parts : e_parts;
        const int b8 = (lane & 15) * 8;
        float v = 0.f;
        #pragma unroll
        for (int k = 0; k < 8; k++) v += part[b8 + k];
        #pragma unroll
        for (int o = 8; o; o >>= 1) v += __shfl_xor_sync(0xffffffffu, v, o);
        const float inv_s = __frcp_rn(__shfl_sync(0xffffffffu, v, 0));
        const float inv_e = __frcp_rn(__shfl_sync(0xffffffffu, v, 16));
        out[row * SEQ + col]               = sv * inv_s;
        out[BATCH * SEQ + row * SEQ + col] = ev * inv_e;
    }

    // ---- rank 0: reduce 128 winner candidates (warp0 = start, warp1 = end) ----
    if (rank == 0 && wid < 2) {
        const float* wv = (wid == 0) ? wsv : wev;
        const int*   wi = (wid == 0) ? wsi : wei;
        float v = wv[lane * 4]; int i = wi[lane * 4];
        #pragma unroll
        for (int k = 1; k < 4; k++) {
            float nv = wv[lane * 4 + k]; int ni = wi[lane * 4 + k];
            if (nv > v || (nv == v && ni < i)) { v = nv; i = ni; }
        }
        #pragma unroll
        for (int o = 16; o; o >>= 1) {
            float ov = __shfl_xor_sync(0xffffffffu, v, o);
            int   oi = __shfl_xor_sync(0xffffffffu, i, o);
            if (ov > v || (ov == v && oi < i)) { v = ov; i = oi; }
        }
        if (lane == 0) {
            if (wid == 0) out[2 * BATCH * SEQ + row]         = (float)i;
            else          out[2 * BATCH * SEQ + BATCH + row] = (float)i;
        }
    }
}

extern "C" void kernel_launch(void* const* d_in, const int* in_sizes, int n_in,
                              void* d_out, int out_size) {
    const float* start_logits = (const float*)d_in[0];
    const float* end_logits   = (const float*)d_in[1];
    float* out = (float*)d_out;
    pred_head_c2<<<BATCH * RANKS, NTC>>>(start_logits, end_logits, out);
}

// round 16
// speedup vs baseline: 1.0968x; 1.0968x over previous
#include <cuda_runtime.h>
#include <math_constants.h>
#include <cstdint>

#define BATCH 16
#define SEQ   4096
#define RANKS 8
#define PER   512
#define NTC   512

__device__ __forceinline__ void st_remote_f32(float* lp, unsigned int r, float v) {
    unsigned int la = (unsigned int)__cvta_generic_to_shared((void*)lp);
    unsigned int ra;
    asm("mapa.shared::cluster.u32 %0, %1, %2;" : "=r"(ra) : "r"(la), "r"(r));
    asm volatile("st.shared::cluster.f32 [%0], %1;" :: "r"(ra), "f"(v) : "memory");
}
__device__ __forceinline__ void st_remote_s32(int* lp, unsigned int r, int v) {
    unsigned int la = (unsigned int)__cvta_generic_to_shared((void*)lp);
    unsigned int ra;
    asm("mapa.shared::cluster.u32 %0, %1, %2;" : "=r"(ra) : "r"(la), "r"(r));
    asm volatile("st.shared::cluster.b32 [%0], %1;" :: "r"(ra), "r"(v) : "memory");
}
#define CLUSTER_SYNC() do { \
    asm volatile("barrier.cluster.arrive.aligned;" ::: "memory"); \
    asm volatile("barrier.cluster.wait.aligned;"   ::: "memory"); } while (0)

__global__ __launch_bounds__(NTC, 1) __cluster_dims__(RANKS, 1, 1)
void pred_head_cluster(const float* __restrict__ start_logits,
                       const float* __restrict__ end_logits,
                       float* __restrict__ out) {
    // LOG-SPACE windows: all scans on raw logits (argmax invariant under exp).
    // pfx_e[0..511]: per-warp prefix-max of end-logit; [512..541]: next-chunk halo prefix
    // sfx_s[32..543]: per-warp suffix-max of start-logit; [2..31]: prev-chunk halo suffix
    __shared__ float pfx_e[544];
    __shared__ float sfx_s[544];
    __shared__ float red[16], red2[16];
    __shared__ float wav[16], wav2[16];
    __shared__ int   wai[16], wai2[16];
    __shared__ float s_parts[RANKS], e_parts[RANKS];
    __shared__ float wsv[RANKS], wev[RANKS];
    __shared__ int   wsi[RANKS], wei[RANKS];

    const int t = threadIdx.x;
    const int lane = t & 31;
    const int wid  = t >> 5;
    unsigned int rank;
    asm("mov.u32 %0, %%cluster_ctarank;" : "=r"(rank));
    const int row = blockIdx.x >> 3;
    const int col = (int)rank * PER + t;
    const float* srow = start_logits + row * SEQ;
    const float* erow = end_logits   + row * SEQ;

    // ---- own logit loads (argmax path starts here, no exp in front) ----
    const float sl = srow[col];
    const float el = erow[col];

    // ---- halo: raw logit max-scans (no exp needed in log space) ----
    if (wid == 1 && lane < 30) {
        // prev chunk [rank*PER-30+lane .. rank*PER-1]: suffix-max of start-logit
        float hv = (rank > 0) ? srow[(int)rank * PER - 30 + lane] : -CUDART_INF_F;
        #pragma unroll
        for (int o = 1; o < 32; o <<= 1) {
            float b = __shfl_down_sync(0x3fffffffu, hv, o);
            if (lane + o < 30) hv = fmaxf(hv, b);
        }
        sfx_s[2 + lane] = hv;
    }
    if (wid == 2 && lane < 30) {
        // next chunk [(rank+1)*PER .. +lane]: prefix-max of end-logit
        float hv = (rank < RANKS - 1) ? erow[((int)rank + 1) * PER + lane] : -CUDART_INF_F;
        #pragma unroll
        for (int o = 1; o < 32; o <<= 1) {
            float a = __shfl_up_sync(0x3fffffffu, hv, o);
            if (lane >= o) hv = fmaxf(hv, a);
        }
        pfx_e[512 + lane] = hv;
    }

    // ---- per-warp prefix/suffix maxima on logits ----
    float pe = el, se_ = el;   // prefix/suffix of end-logit
    float ps_ = sl, ssx = sl;  // prefix/suffix of start-logit
    #pragma unroll
    for (int o = 1; o < 32; o <<= 1) {
        float a = __shfl_up_sync(0xffffffffu, pe, o);    if (lane >= o)     pe  = fmaxf(pe, a);
        float b = __shfl_down_sync(0xffffffffu, se_, o); if (lane + o < 32) se_ = fmaxf(se_, b);
        float c = __shfl_up_sync(0xffffffffu, ps_, o);   if (lane >= o)     ps_ = fmaxf(ps_, c);
        float d = __shfl_down_sync(0xffffffffu, ssx, o); if (lane + o < 32) ssx = fmaxf(ssx, d);
    }
    pfx_e[t] = pe;
    sfx_s[32 + t] = ssx;

    // ---- exps (MUFU) — needed only for probs/sums; overlaps the scan pipe ----
    const float sv = __expf(sl);
    const float ev = __expf(el);

    // ---- per-warp partial sums ----
    float a = sv, c = ev;
    #pragma unroll
    for (int o = 16; o; o >>= 1) {
        a += __shfl_xor_sync(0xffffffffu, a, o);
        c += __shfl_xor_sync(0xffffffffu, c, o);
    }
    if (lane == 0) { red[wid] = a; red2[wid] = c; }

    __syncthreads();   // #1: prefix/suffix + halos + sum partials visible CTA-wide

    // ---- width-31 windows via prefix/suffix decomposition (log space) ----
    // F[i] = max e-logit[i..i+30]; B[j] = max s-logit[j-30..j]
    const float pe30 = __shfl_sync(0xffffffffu, pe, 30);
    const float ss1  = __shfl_sync(0xffffffffu, ssx, 1);
    float F, Bv;
    if (lane == 0)       F = pe30;
    else if (lane == 1)  F = se_;
    else                 F = fmaxf(se_, pfx_e[t + 30]);
    if (lane == 31)      Bv = ss1;
    else if (lane == 30) Bv = ps_;
    else                 Bv = fmaxf(ps_, sfx_s[t + 2]);

    // ---- log-space scores + warp argmax (dual, first-index tie-break) ----
    float bsv = sl + F;  int bsi = col;
    float bev = el + Bv; int bei = col;
    #pragma unroll
    for (int o = 16; o; o >>= 1) {
        float ov = __shfl_xor_sync(0xffffffffu, bsv, o);
        int   oi = __shfl_xor_sync(0xffffffffu, bsi, o);
        if (ov > bsv || (ov == bsv && oi < bsi)) { bsv = ov; bsi = oi; }
        float ov2 = __shfl_xor_sync(0xffffffffu, bev, o);
        int   oi2 = __shfl_xor_sync(0xffffffffu, bei, o);
        if (ov2 > bev || (ov2 == bev && oi2 < bei)) { bev = ov2; bei = oi2; }
    }
    if (lane == 0) { wav[wid] = bsv; wai[wid] = bsi; wav2[wid] = bev; wai2[wid] = bei; }

    __syncthreads();   // #2: warp partials visible

    // ---- parallel final reductions + remote pushes (all BEFORE the single cluster sync) ----
    if (wid == 0) {
        float aa = (lane < 16) ? red[lane]  : 0.f;
        float cc = (lane < 16) ? red2[lane] : 0.f;
        #pragma unroll
        for (int o = 8; o; o >>= 1) {
            aa += __shfl_xor_sync(0xffffffffu, aa, o);
            cc += __shfl_xor_sync(0xffffffffu, cc, o);
        }
        if (lane < 8)        st_remote_f32(&s_parts[rank], (unsigned int)lane, aa);
        else if (lane < 16)  st_remote_f32(&e_parts[rank], (unsigned int)(lane - 8), cc);
    } else if (wid == 1) {
        float v1 = (lane < 16) ? wav[lane] : -CUDART_INF_F;
        int   i1 = (lane < 16) ? wai[lane] : 0x7fffffff;
        #pragma unroll
        for (int o = 8; o; o >>= 1) {
            float ov = __shfl_xor_sync(0xffffffffu, v1, o);
            int   oi = __shfl_xor_sync(0xffffffffu, i1, o);
            if (ov > v1 || (ov == v1 && oi < i1)) { v1 = ov; i1 = oi; }
        }
        if (lane == 0) { st_remote_f32(&wsv[rank], 0u, v1); st_remote_s32(&wsi[rank], 0u, i1); }
    } else if (wid == 2) {
        float v2 = (lane < 16) ? wav2[lane] : -CUDART_INF_F;
        int   i2 = (lane < 16) ? wai2[lane] : 0x7fffffff;
        #pragma unroll
        for (int o = 8; o; o >>= 1) {
            float ov = __shfl_xor_sync(0xffffffffu, v2, o);
            int   oi = __shfl_xor_sync(0xffffffffu, i2, o);
            if (ov > v2 || (ov == v2 && oi < i2)) { v2 = ov; i2 = oi; }
        }
        if (lane == 0) { st_remote_f32(&wev[rank], 0u, v2); st_remote_s32(&wei[rank], 0u, i2); }
    }

    CLUSTER_SYNC();   // the ONLY cluster sync

    // ---- probs: every warp redundantly computes global inv-sums, then STG ----
    {
        float v = (lane < 8) ? s_parts[lane] : ((lane < 16) ? e_parts[lane - 8] : 0.f);
        v += __shfl_xor_sync(0xffffffffu, v, 4);
        v += __shfl_xor_sync(0xffffffffu, v, 2);
        v += __shfl_xor_sync(0xffffffffu, v, 1);
        const float inv_s = __frcp_rn(__shfl_sync(0xffffffffu, v, 0));
        const float inv_e = __frcp_rn(__shfl_sync(0xffffffffu, v, 8));
        out[row * SEQ + col]               = sv * inv_s;
        out[BATCH * SEQ + row * SEQ + col] = ev * inv_e;
    }

    // ---- rank 0 reduces the 8 cluster winners ----
    if (rank == 0 && wid == 0) {
        float v1 = (lane < 8) ? wsv[lane] : -CUDART_INF_F;
        int   i1 = (lane < 8) ? wsi[lane] : 0x7fffffff;
        float v2 = (lane < 8) ? wev[lane] : -CUDART_INF_F;
        int   i2 = (lane < 8) ? wei[lane] : 0x7fffffff;
        #pragma unroll
        for (int o = 4; o; o >>= 1) {
            float ov = __shfl_xor_sync(0xffffffffu, v1, o);
            int   oi = __shfl_xor_sync(0xffffffffu, i1, o);
            if (ov > v1 || (ov == v1 && oi < i1)) { v1 = ov; i1 = oi; }
            float ov2 = __shfl_xor_sync(0xffffffffu, v2, o);
            int   oi2 = __shfl_xor_sync(0xffffffffu, i2, o);
            if (ov2 > v2 || (ov2 == v2 && oi2 < i2)) { v2 = ov2; i2 = oi2; }
        }
        if (lane == 0) {
            out[2 * BATCH * SEQ + row]         = (float)i1;
            out[2 * BATCH * SEQ + BATCH + row] = (float)i2;
        }
    }
}

extern "C" void kernel_launch(void* const* d_in, const int* in_sizes, int n_in,
                              void* d_out, int out_size) {
    const float* start_logits = (const float*)d_in[0];
    const float* end_logits   = (const float*)d_in[1];
    float* out = (float*)d_out;
    pred_head_cluster<<<BATCH * RANKS, NTC>>>(start_logits, end_logits, out);
}